// round 9
// baseline (speedup 1.0000x reference)
#include <cuda_runtime.h>
#include <cuda_bf16.h>
#include <cstdint>
#include <cstddef>

#define NQ 128
#define CDIM 640
#define NP 1024

// A: 128 rows x 648 bf16 (row 1296 B = 324 words, 324%32==4 -> LDSM conflict-free)
#define A_ROW_B 1296
#define A_BYTES (128 * A_ROW_B)          /* 165888 */
#define B_OFF   A_BYTES
#define B_ROW_B 144                      /* 72 bf16 = 36 words, 36%32==4 */
#define B_BUF_B (128 * B_ROW_B)          /* 18432 */
#define N_STAGE 3
#define RS_OFF  (B_OFF + N_STAGE * B_BUF_B)   /* 221184 */
#define MAIN_SMEM (RS_OFF + (8 * 32 + 8) * 4) /* 222240 */
#define P2_SMEM ((640 * 65 + 256 + 64) * 4)

// ---------------- device scratch (static) -----------------------------------
__device__ __align__(16) __nv_bfloat16 g_q[(size_t)NQ * NP * CDIM]; // [q][n][c]
__device__ __align__(16) __nv_bfloat16 g_s[(size_t)NP * CDIM];      // [n][c]
__device__ float g_part[NQ * 8];

// ---------------- helpers ----------------------------------------------------
__device__ __forceinline__ uint32_t smem_u32(const void* p) {
    uint32_t a;
    asm("{ .reg .u64 t; cvta.to.shared.u64 t, %1; cvt.u32.u64 %0, t; }" : "=r"(a) : "l"(p));
    return a;
}
#define CP_ASYNC16(dst, src) \
    asm volatile("cp.async.cg.shared.global [%0], [%1], 16;" :: "r"(dst), "l"(src) : "memory")
#define CP_COMMIT() asm volatile("cp.async.commit_group;" ::: "memory")
#define CP_WAIT(n)  asm volatile("cp.async.wait_group %0;" :: "n"(n) : "memory")

__device__ __forceinline__ void ldsm_x4(uint32_t* r, uint32_t a) {
    asm volatile("ldmatrix.sync.aligned.m8n8.x4.shared.b16 {%0,%1,%2,%3}, [%4];"
        : "=r"(r[0]), "=r"(r[1]), "=r"(r[2]), "=r"(r[3]) : "r"(a));
}
__device__ __forceinline__ void mma16816(float* c, const uint32_t* a, const uint32_t* b) {
    asm volatile(
        "mma.sync.aligned.m16n8k16.row.col.f32.bf16.bf16.f32 "
        "{%0,%1,%2,%3}, {%4,%5,%6,%7}, {%8,%9}, {%0,%1,%2,%3};"
        : "+f"(c[0]), "+f"(c[1]), "+f"(c[2]), "+f"(c[3])
        : "r"(a[0]), "r"(a[1]), "r"(a[2]), "r"(a[3]), "r"(b[0]), "r"(b[1]));
}

// ---------------- P1: support prototype + L2 norm -> g_s bf16 [n][c] --------
__global__ void prep_support(const float* __restrict__ sup) {
    __shared__ float red[256];
    __shared__ float inv[64];
    int t = threadIdx.x, r = t >> 6, ml = t & 63;
    int m0 = blockIdx.x * 64;
    float ssq = 0.f;
    for (int c = r; c < CDIM; c += 4) {
        float s = 0.f;
        #pragma unroll
        for (int sh = 0; sh < 5; sh++) s += sup[((size_t)sh * CDIM + c) * NP + m0 + ml];
        float p = s * 0.2f;
        ssq += p * p;
    }
    red[t] = ssq;
    __syncthreads();
    if (t < 64)
        inv[t] = 1.f / fmaxf(sqrtf(red[t] + red[t + 64] + red[t + 128] + red[t + 192]), 1e-12f);
    __syncthreads();
    float iv = inv[ml];
    for (int c = r; c < CDIM; c += 4) {
        float s = 0.f;
        #pragma unroll
        for (int sh = 0; sh < 5; sh++) s += sup[((size_t)sh * CDIM + c) * NP + m0 + ml];
        g_s[(size_t)(m0 + ml) * CDIM + c] = __float2bfloat16(s * 0.2f * iv);
    }
}

// ---------------- P2: query normalize + transpose -> g_q bf16 [q][n][c] -----
__global__ void __launch_bounds__(256, 1) prep_query(const float* __restrict__ qf) {
    extern __shared__ unsigned char sm2[];
    float* tile = reinterpret_cast<float*>(sm2);   // [640][65]
    float* red  = tile + 640 * 65;
    float* inv  = red + 256;
    int t = threadIdx.x, r = t >> 6, nl = t & 63;
    int q = blockIdx.y, n0 = blockIdx.x * 64;
    const float* src = qf + (size_t)q * CDIM * NP + n0;
    float ssq = 0.f;
    for (int c = r; c < CDIM; c += 4) {
        float v = src[(size_t)c * NP + nl];
        tile[c * 65 + nl] = v;
        ssq += v * v;
    }
    red[t] = ssq;
    __syncthreads();
    if (t < 64)
        inv[t] = 1.f / fmaxf(sqrtf(red[t] + red[t + 64] + red[t + 128] + red[t + 192]), 1e-12f);
    __syncthreads();
    for (int n = 0; n < 64; n++) {
        float iv = inv[n];
        __nv_bfloat162* row =
            reinterpret_cast<__nv_bfloat162*>(g_q + ((size_t)q * NP + n0 + n) * CDIM);
        for (int p = t; p < 320; p += 256) {
            int c = p << 1;
            __nv_bfloat162 o;
            o.x = __float2bfloat16(tile[c * 65 + n] * iv);
            o.y = __float2bfloat16(tile[(c + 1) * 65 + n] * iv);
            row[p] = o;
        }
    }
}

// ---------------- P3: main HMMA GEMM + rowmax --------------------------------
// bid = q*8 + mt. A resident (128x640). B streamed: 8 N-tiles x 10 K-chunks
// = 80 steps, 3-stage cp.async pipeline, ldmatrix fragment loads.
__global__ void __launch_bounds__(256, 1) sim_kernel() {
    extern __shared__ unsigned char sm[];
    const uint32_t sbase = smem_u32(sm);
    const int tid = threadIdx.x, wid = tid >> 5, lid = tid & 31;
    const int g = lid >> 2, t = lid & 3;
    const int mat = lid >> 3, mi = lid & 7;           // ldmatrix lane roles
    const int wm = (wid >> 1) * 32, wn = (wid & 1) * 64;
    const int bid = blockIdx.x, q = bid >> 3, mt = bid & 7;

    // ---- A tile via cp.async (own group, overlaps B prefetch) ----
    const __nv_bfloat16* qa = g_q + ((size_t)q * NP + mt * 128) * CDIM;
    for (int i = tid; i < 10240; i += 256) {          // 10240 x 16B
        int m = i / 80, v = i % 80;
        CP_ASYNC16(sbase + m * A_ROW_B + v * 16, qa + (size_t)m * CDIM + v * 8);
    }
    CP_COMMIT();

    // ---- B chunk loader: step j -> nt=j/10, kc=j%10, buffer j%3 ----
    const __nv_bfloat16* Bsrc = g_s;
    auto loadB = [&](int j, int buf) {
        int nt = j / 10, kc = j - nt * 10;
        int n0 = nt << 7;
        uint32_t dstb = sbase + B_OFF + buf * B_BUF_B;
        #pragma unroll
        for (int it = 0; it < 4; it++) {
            int idx = tid + it * 256;
            int r = idx >> 3, c = idx & 7;
            CP_ASYNC16(dstb + r * B_ROW_B + c * 16,
                       Bsrc + (size_t)(n0 + r) * CDIM + kc * 64 + c * 8);
        }
        CP_COMMIT();
    };
    loadB(0, 0);
    loadB(1, 1);

    // ---- per-lane ldmatrix base addresses ----
    // A frag (m16k16) x4 mats: row = m0 + (mat&1)*8 + mi, colbyte = (mat>>1)*16
    uint32_t abase[2];
    #pragma unroll
    for (int ms = 0; ms < 2; ms++)
        abase[ms] = sbase + (wm + ms * 16 + (mat & 1) * 8 + mi) * A_ROW_B + (mat >> 1) * 16;
    // B frag pair (two n8k16) x4 mats: row = n0p + (mat>>1)*8 + mi, colbyte = (mat&1)*16
    uint32_t bloff[4];
    #pragma unroll
    for (int p = 0; p < 4; p++)
        bloff[p] = (wn + p * 16 + (mat >> 1) * 8 + mi) * B_ROW_B + (mat & 1) * 16;

    float acc[2][8][4];
    float rmax4[4] = {-3.0e38f, -3.0e38f, -3.0e38f, -3.0e38f};
    int buf = 0, wbuf = 2, kc = 0;

    for (int j = 0; j < 80; j++) {
        if (j < 79) CP_WAIT(1); else CP_WAIT(0);
        __syncthreads();   // buf j ready everywhere; all step j-1 reads done
        if (j < 78) {      // overwrites buffer (j+2)%3 == buffer read at j-1: safe
            loadB(j + 2, wbuf);
            if (++wbuf == N_STAGE) wbuf = 0;
        }

        if (kc == 0) {
            if (j > 0) {
                #pragma unroll
                for (int ms = 0; ms < 2; ms++)
                    #pragma unroll
                    for (int ns = 0; ns < 8; ns++) {
                        rmax4[ms * 2 + 0] = fmaxf(rmax4[ms * 2 + 0],
                                                  fmaxf(acc[ms][ns][0], acc[ms][ns][1]));
                        rmax4[ms * 2 + 1] = fmaxf(rmax4[ms * 2 + 1],
                                                  fmaxf(acc[ms][ns][2], acc[ms][ns][3]));
                    }
            }
            #pragma unroll
            for (int ms = 0; ms < 2; ms++)
                #pragma unroll
                for (int ns = 0; ns < 8; ns++)
                    #pragma unroll
                    for (int v = 0; v < 4; v++) acc[ms][ns][v] = 0.f;
        }

        const uint32_t bb = sbase + B_OFF + buf * B_BUF_B;
        const uint32_t akb = kc * 128;                 // kc*64 elems * 2B
        #pragma unroll
        for (int ks = 0; ks < 4; ks++) {
            uint32_t a0[4], a1[4], br[4][4];
            ldsm_x4(a0, abase[0] + akb + ks * 32);
            ldsm_x4(a1, abase[1] + akb + ks * 32);
            #pragma unroll
            for (int p = 0; p < 4; p++) ldsm_x4(br[p], bb + bloff[p] + ks * 32);
            #pragma unroll
            for (int p = 0; p < 4; p++) {
                mma16816(acc[0][2 * p + 0], a0, &br[p][0]);
                mma16816(acc[0][2 * p + 1], a0, &br[p][2]);
                mma16816(acc[1][2 * p + 0], a1, &br[p][0]);
                mma16816(acc[1][2 * p + 1], a1, &br[p][2]);
            }
        }
        if (++buf == N_STAGE) buf = 0;
        if (++kc == 10) kc = 0;
    }

    // final N-tile rowmax fold
    #pragma unroll
    for (int ms = 0; ms < 2; ms++)
        #pragma unroll
        for (int ns = 0; ns < 8; ns++) {
            rmax4[ms * 2 + 0] = fmaxf(rmax4[ms * 2 + 0], fmaxf(acc[ms][ns][0], acc[ms][ns][1]));
            rmax4[ms * 2 + 1] = fmaxf(rmax4[ms * 2 + 1], fmaxf(acc[ms][ns][2], acc[ms][ns][3]));
        }

    // reduce: lanes t (same rows) -> warpN pairs -> sum of 128 rowmaxes
    float* rs = reinterpret_cast<float*>(sm + RS_OFF);
    #pragma unroll
    for (int m4 = 0; m4 < 4; m4++) {
        float v = rmax4[m4];
        v = fmaxf(v, __shfl_xor_sync(0xffffffffu, v, 1));
        v = fmaxf(v, __shfl_xor_sync(0xffffffffu, v, 2));
        rmax4[m4] = v;
    }
    if (t == 0) {
        rs[wid * 32 + g]      = rmax4[0];
        rs[wid * 32 + 8 + g]  = rmax4[1];
        rs[wid * 32 + 16 + g] = rmax4[2];
        rs[wid * 32 + 24 + g] = rmax4[3];
    }
    __syncthreads();
    if (tid < 128) {
        int wmi = tid >> 5, r = tid & 31;
        float v = fmaxf(rs[(2 * wmi) * 32 + r], rs[(2 * wmi + 1) * 32 + r]);
        #pragma unroll
        for (int o = 16; o; o >>= 1) v += __shfl_xor_sync(0xffffffffu, v, o);
        if ((tid & 31) == 0) rs[256 + (tid >> 5)] = v;
    }
    __syncthreads();
    if (tid == 0) g_part[bid] = rs[256] + rs[257] + rs[258] + rs[259];
}

// ---------------- P4: deterministic reduce -> scores ------------------------
__global__ void finalize_kernel(float* __restrict__ out) {
    int q = threadIdx.x;
    float s = 0.f;
    #pragma unroll
    for (int mt = 0; mt < 8; mt++) s += g_part[q * 8 + mt];
    out[q] = s * (1.0f / 1024.0f);
}

// ---------------- launch ------------------------------------------------------
extern "C" void kernel_launch(void* const* d_in, const int* in_sizes, int n_in,
                              void* d_out, int out_size) {
    const float* qf = (const float*)d_in[0];
    const float* sf = (const float*)d_in[1];
    float* out = (float*)d_out;
    cudaFuncSetAttribute(prep_query, cudaFuncAttributeMaxDynamicSharedMemorySize, P2_SMEM);
    cudaFuncSetAttribute(sim_kernel, cudaFuncAttributeMaxDynamicSharedMemorySize, MAIN_SMEM);
    prep_support<<<16, 256>>>(sf);
    dim3 g2(16, 128);
    prep_query<<<g2, 256, P2_SMEM>>>(qf);
    sim_kernel<<<1024, 256, MAIN_SMEM>>>();
    finalize_kernel<<<1, 128>>>(out);
}

// round 10
// speedup vs baseline: 1.4300x; 1.4300x over previous
#include <cuda_runtime.h>
#include <cuda_bf16.h>
#include <cstdint>
#include <cstddef>

#define NQ 128
#define CDIM 640
#define NP 1024

// A: 128 rows x 648 bf16 (row 1296 B; 1296%128==16 -> LDSM conflict-free)
#define A_ROW_B 1296
#define A_BYTES (128 * A_ROW_B)               /* 165888 */
#define B_OFF   A_BYTES
#define B_ROW_B 144                           /* 144%128==16 -> conflict-free */
#define B_BUF_B (128 * B_ROW_B)               /* 18432 */
#define N_STAGE 3
#define RS_OFF  (B_OFF + N_STAGE * B_BUF_B)   /* 221184 */
#define MAIN_SMEM (RS_OFF + (8 * 32 + 8) * 4)
#define P2_SMEM ((640 * 65 + 256 + 64) * 4)

__device__ __align__(16) __nv_bfloat16 g_q[(size_t)NQ * NP * CDIM];
__device__ __align__(16) __nv_bfloat16 g_s[(size_t)NP * CDIM];
__device__ float g_part[NQ * 8];

__device__ __forceinline__ uint32_t smem_u32(const void* p) {
    uint32_t a;
    asm("{ .reg .u64 t; cvta.to.shared.u64 t, %1; cvt.u32.u64 %0, t; }" : "=r"(a) : "l"(p));
    return a;
}
#define CP_ASYNC16(dst, src) \
    asm volatile("cp.async.cg.shared.global [%0], [%1], 16;" :: "r"(dst), "l"(src) : "memory")
#define CP_COMMIT() asm volatile("cp.async.commit_group;" ::: "memory")
#define CP_WAIT(n)  asm volatile("cp.async.wait_group %0;" :: "n"(n) : "memory")

__device__ __forceinline__ void ldsm_x4(uint32_t* r, uint32_t a) {
    asm volatile("ldmatrix.sync.aligned.m8n8.x4.shared.b16 {%0,%1,%2,%3}, [%4];"
        : "=r"(r[0]), "=r"(r[1]), "=r"(r[2]), "=r"(r[3]) : "r"(a));
}
__device__ __forceinline__ void mma16816(float* c, const uint32_t* a, const uint32_t* b) {
    asm volatile(
        "mma.sync.aligned.m16n8k16.row.col.f32.bf16.bf16.f32 "
        "{%0,%1,%2,%3}, {%4,%5,%6,%7}, {%8,%9}, {%0,%1,%2,%3};"
        : "+f"(c[0]), "+f"(c[1]), "+f"(c[2]), "+f"(c[3])
        : "r"(a[0]), "r"(a[1]), "r"(a[2]), "r"(a[3]), "r"(b[0]), "r"(b[1]));
}

// ---------------- P1: support prototype + L2 norm --------------------------
__global__ void prep_support(const float* __restrict__ sup) {
    __shared__ float red[256];
    __shared__ float inv[64];
    int t = threadIdx.x, r = t >> 6, ml = t & 63;
    int m0 = blockIdx.x * 64;
    float ssq = 0.f;
    for (int c = r; c < CDIM; c += 4) {
        float s = 0.f;
        #pragma unroll
        for (int sh = 0; sh < 5; sh++) s += sup[((size_t)sh * CDIM + c) * NP + m0 + ml];
        float p = s * 0.2f;
        ssq += p * p;
    }
    red[t] = ssq;
    __syncthreads();
    if (t < 64)
        inv[t] = 1.f / fmaxf(sqrtf(red[t] + red[t + 64] + red[t + 128] + red[t + 192]), 1e-12f);
    __syncthreads();
    float iv = inv[ml];
    for (int c = r; c < CDIM; c += 4) {
        float s = 0.f;
        #pragma unroll
        for (int sh = 0; sh < 5; sh++) s += sup[((size_t)sh * CDIM + c) * NP + m0 + ml];
        g_s[(size_t)(m0 + ml) * CDIM + c] = __float2bfloat16(s * 0.2f * iv);
    }
}

// ---------------- P2: query normalize + transpose --------------------------
__global__ void __launch_bounds__(256, 1) prep_query(const float* __restrict__ qf) {
    extern __shared__ unsigned char sm2[];
    float* tile = reinterpret_cast<float*>(sm2);   // [640][65]
    float* red  = tile + 640 * 65;
    float* inv  = red + 256;
    int t = threadIdx.x, r = t >> 6, nl = t & 63;
    int q = blockIdx.y, n0 = blockIdx.x * 64;
    const float* src = qf + (size_t)q * CDIM * NP + n0;
    float ssq = 0.f;
    for (int c = r; c < CDIM; c += 4) {
        float v = src[(size_t)c * NP + nl];
        tile[c * 65 + nl] = v;
        ssq += v * v;
    }
    red[t] = ssq;
    __syncthreads();
    if (t < 64)
        inv[t] = 1.f / fmaxf(sqrtf(red[t] + red[t + 64] + red[t + 128] + red[t + 192]), 1e-12f);
    __syncthreads();
    for (int n = 0; n < 64; n++) {
        float iv = inv[n];
        __nv_bfloat162* row =
            reinterpret_cast<__nv_bfloat162*>(g_q + ((size_t)q * NP + n0 + n) * CDIM);
        for (int p = t; p < 320; p += 256) {
            int c = p << 1;
            __nv_bfloat162 o;
            o.x = __float2bfloat16(tile[c * 65 + n] * iv);
            o.y = __float2bfloat16(tile[(c + 1) * 65 + n] * iv);
            row[p] = o;
        }
    }
}

// ---------------- P3: main HMMA GEMM + rowmax -------------------------------
// A resident; B streamed 8 N-tiles x 10 K-chunks. 3 buffers, 2 loads in
// flight (issue-then-wait), ldmatrix fragments, 2 syncs/step.
__global__ void __launch_bounds__(256, 1) sim_kernel() {
    extern __shared__ unsigned char sm[];
    const uint32_t sbase = smem_u32(sm);
    const int tid = threadIdx.x, wid = tid >> 5, lid = tid & 31;
    const int g = lid >> 2, t = lid & 3;
    const int mat = lid >> 3, mi = lid & 7;
    const int wm = (wid >> 1) * 32, wn = (wid & 1) * 64;
    const int bid = blockIdx.x, q = bid >> 3, mt = bid & 7;

    // A tile: own cp.async group (overlaps B0/B1 fetch)
    const __nv_bfloat16* qa = g_q + ((size_t)q * NP + mt * 128) * CDIM;
    for (int i = tid; i < 10240; i += 256) {
        int m = i / 80, v = i % 80;
        CP_ASYNC16(sbase + m * A_ROW_B + v * 16, qa + (size_t)m * CDIM + v * 8);
    }
    CP_COMMIT();

    const int r8 = tid >> 3, c8 = tid & 7;   // B load roles (fixed)
    auto loadB = [&](int n0, int kc, int buf) {
        uint32_t dstb = sbase + B_OFF + buf * B_BUF_B;
        const __nv_bfloat16* s0 = g_s + (size_t)n0 * CDIM + kc * 64 + c8 * 8;
        #pragma unroll
        for (int it = 0; it < 4; it++) {
            int r = r8 + it * 32;
            CP_ASYNC16(dstb + r * B_ROW_B + c8 * 16, s0 + (size_t)r * CDIM);
        }
        CP_COMMIT();
    };
    loadB(0, 0, 0);
    loadB(0, 1, 1);

    // ldmatrix base addresses (mapping verified in round 9)
    uint32_t abase[2];
    #pragma unroll
    for (int ms = 0; ms < 2; ms++)
        abase[ms] = sbase + (wm + ms * 16 + (mat & 1) * 8 + mi) * A_ROW_B + (mat >> 1) * 16;
    uint32_t bloff[4];
    #pragma unroll
    for (int p = 0; p < 4; p++)
        bloff[p] = (wn + p * 16 + (mat >> 1) * 8 + mi) * B_ROW_B + (mat & 1) * 16;

    float acc[2][8][4];
    float rmax4[4] = {-3.0e38f, -3.0e38f, -3.0e38f, -3.0e38f};
    int cbuf = 0, wbuf = 2;       // compute buffer, write buffer
    int fnt = 0, fkc = 2;         // next fetch (chunk index j+2)
    int j = 0;

    for (int nt = 0; nt < 8; nt++) {
        #pragma unroll
        for (int ms = 0; ms < 2; ms++)
            #pragma unroll
            for (int ns = 0; ns < 8; ns++)
                #pragma unroll
                for (int v = 0; v < 4; v++) acc[ms][ns][v] = 0.f;

        for (int kc = 0; kc < 10; kc++, j++) {
            // issue prefetch j+2 FIRST, then bounded wait
            if (j < 78) {
                loadB(fnt << 7, fkc, wbuf);
                if (++wbuf == N_STAGE) wbuf = 0;
                if (++fkc == 10) { fkc = 0; fnt++; }
                CP_WAIT(2);                    // B_j complete (A too at j=0)
            } else if (j == 78) { CP_WAIT(1); }
            else                { CP_WAIT(0); }
            __syncthreads();                   // buf j visible to all

            const uint32_t bb = sbase + B_OFF + cbuf * B_BUF_B;
            const uint32_t akb = (uint32_t)kc * 128;
            #pragma unroll
            for (int ks = 0; ks < 4; ks++) {
                uint32_t a0[4], a1[4], br[4];
                ldsm_x4(a0, abase[0] + akb + ks * 32);
                ldsm_x4(a1, abase[1] + akb + ks * 32);
                #pragma unroll
                for (int p = 0; p < 4; p++) {
                    ldsm_x4(br, bb + bloff[p] + ks * 32);
                    mma16816(acc[0][2 * p + 0], a0, &br[0]);
                    mma16816(acc[0][2 * p + 1], a0, &br[2]);
                    mma16816(acc[1][2 * p + 0], a1, &br[0]);
                    mma16816(acc[1][2 * p + 1], a1, &br[2]);
                }
            }
            if (++cbuf == N_STAGE) cbuf = 0;
            __syncthreads();                   // reads done before buf reuse
        }
        // fold this N-tile's rowmax
        #pragma unroll
        for (int ms = 0; ms < 2; ms++)
            #pragma unroll
            for (int ns = 0; ns < 8; ns++) {
                rmax4[ms * 2 + 0] = fmaxf(rmax4[ms * 2 + 0], fmaxf(acc[ms][ns][0], acc[ms][ns][1]));
                rmax4[ms * 2 + 1] = fmaxf(rmax4[ms * 2 + 1], fmaxf(acc[ms][ns][2], acc[ms][ns][3]));
            }
    }

    // reduce: lanes t (same rows) -> warpN pairs -> sum of 128 rowmaxes
    float* rs = reinterpret_cast<float*>(sm + RS_OFF);
    #pragma unroll
    for (int m4 = 0; m4 < 4; m4++) {
        float v = rmax4[m4];
        v = fmaxf(v, __shfl_xor_sync(0xffffffffu, v, 1));
        v = fmaxf(v, __shfl_xor_sync(0xffffffffu, v, 2));
        rmax4[m4] = v;
    }
    if (t == 0) {
        rs[wid * 32 + g]      = rmax4[0];
        rs[wid * 32 + 8 + g]  = rmax4[1];
        rs[wid * 32 + 16 + g] = rmax4[2];
        rs[wid * 32 + 24 + g] = rmax4[3];
    }
    __syncthreads();
    if (tid < 128) {
        int wmi = tid >> 5, r = tid & 31;
        float v = fmaxf(rs[(2 * wmi) * 32 + r], rs[(2 * wmi + 1) * 32 + r]);
        #pragma unroll
        for (int o = 16; o; o >>= 1) v += __shfl_xor_sync(0xffffffffu, v, o);
        if ((tid & 31) == 0) rs[256 + (tid >> 5)] = v;
    }
    __syncthreads();
    if (tid == 0) g_part[bid] = rs[256] + rs[257] + rs[258] + rs[259];
}

// ---------------- P4: deterministic reduce ----------------------------------
__global__ void finalize_kernel(float* __restrict__ out) {
    int q = threadIdx.x;
    float s = 0.f;
    #pragma unroll
    for (int mt = 0; mt < 8; mt++) s += g_part[q * 8 + mt];
    out[q] = s * (1.0f / 1024.0f);
}

extern "C" void kernel_launch(void* const* d_in, const int* in_sizes, int n_in,
                              void* d_out, int out_size) {
    const float* qf = (const float*)d_in[0];
    const float* sf = (const float*)d_in[1];
    float* out = (float*)d_out;
    cudaFuncSetAttribute(prep_query, cudaFuncAttributeMaxDynamicSharedMemorySize, P2_SMEM);
    cudaFuncSetAttribute(sim_kernel, cudaFuncAttributeMaxDynamicSharedMemorySize, MAIN_SMEM);
    prep_support<<<16, 256>>>(sf);
    dim3 g2(16, 128);
    prep_query<<<g2, 256, P2_SMEM>>>(qf);
    sim_kernel<<<1024, 256, MAIN_SMEM>>>();
    finalize_kernel<<<1, 128>>>(out);
}